// round 3
// baseline (speedup 1.0000x reference)
#include <cuda_runtime.h>
#include <math.h>

#define BS   8
#define HW   1024
#define STEP 20
#define NS   51          // hw // STEP
#define NP   512         // model points
#define NPAIR (NP / 2)   // 256 packed GT pairs
#define NBLK (BS * NS)   // 408 hypotheses
#define SCORING_WEIGHT 0.01f

// Scratch (no allocations allowed)
__device__ float    g_part[NBLK];
__device__ unsigned g_count = 0;   // last-block-done counter; self-resetting

// ---------------------------------------------------------------------------
// Single fused kernel: one block per (batch, sample) hypothesis.
//  - per-block recompute of GT cloud into shared, packed for f32x2 math:
//    pair i stores [x0,x1, y0,y1, z0,z1, w0,w1] where (x,y,z)=-2*g, w=|g|^2
//  - inner loop: per 2 GT candidates = 2x LDS.128 + 3x fma.rn.f32x2 + 2x FMNMX
//  - block sum of dmin, last finishing block reduces the 408 partials.
// ---------------------------------------------------------------------------
__global__ __launch_bounds__(NP, 2) void fused_kernel(
    const float* __restrict__ pred_r,
    const float* __restrict__ pred_t,
    const float* __restrict__ pred_s,
    const float* __restrict__ gt_r,
    const float* __restrict__ gt_t,
    const float* __restrict__ model,
    float* __restrict__ out)
{
    __shared__ float sg[NP * 4];   // 8 KB: 256 pairs x 32 bytes
    __shared__ float red[NP];
    __shared__ bool  s_last;

    int blk = blockIdx.x;
    int b   = blk / NS;
    int pix = (blk % NS) * STEP;
    int tid = threadIdx.x;

    const float* m  = model + b * 3 * NP;
    float mx = m[tid], my = m[NP + tid], mz = m[2 * NP + tid];

    // ---- GT point for this thread -> packed shared ----
    {
        const float* R = gt_r + b * 9;
        const float* T = gt_t + b * 3;
        float gx = fmaf(R[0], mx, fmaf(R[1], my, fmaf(R[2], mz, T[0])));
        float gy = fmaf(R[3], mx, fmaf(R[4], my, fmaf(R[5], mz, T[1])));
        float gz = fmaf(R[6], mx, fmaf(R[7], my, fmaf(R[8], mz, T[2])));
        float gn = fmaf(gx, gx, fmaf(gy, gy, gz * gz));
        float* p = sg + 8 * (tid >> 1) + (tid & 1);
        p[0] = -2.0f * gx;
        p[2] = -2.0f * gy;
        p[4] = -2.0f * gz;
        p[6] = gn;
    }

    // ---- pose from predictions (tiny, redundant per thread) ----
    const float* pr = pred_r + b * 4 * HW + pix;
    float q0 = pr[0], q1 = pr[HW], q2 = pr[2 * HW], q3 = pr[3 * HW];
    float inv = rsqrtf(q0 * q0 + q1 * q1 + q2 * q2 + q3 * q3);
    q0 *= inv; q1 *= inv; q2 *= inv; q3 *= inv;

    float R00 = 1.0f - 2.0f * (q2 * q2 + q3 * q3);
    float R01 = 2.0f * (q1 * q2 - q0 * q3);
    float R02 = 2.0f * (q0 * q2 + q1 * q3);
    float R10 = 2.0f * (q1 * q2 + q3 * q0);
    float R11 = 1.0f - 2.0f * (q1 * q1 + q3 * q3);
    float R12 = 2.0f * (q2 * q3 - q0 * q1);
    float R20 = 2.0f * (q1 * q3 - q0 * q2);
    float R21 = 2.0f * (q0 * q1 + q2 * q3);
    float R22 = 1.0f - 2.0f * (q1 * q1 + q2 * q2);

    const float* pt = pred_t + b * 3 * HW + pix;
    float px = fmaf(R00, mx, fmaf(R01, my, fmaf(R02, mz, pt[0])));
    float py = fmaf(R10, mx, fmaf(R11, my, fmaf(R12, mz, pt[HW])));
    float pz = fmaf(R20, mx, fmaf(R21, my, fmaf(R22, mz, pt[2 * HW])));
    float pn = fmaf(px, px, fmaf(py, py, pz * pz));

    __syncthreads();

    // ---- broadcast-pack the query point into f32x2 registers ----
    unsigned long long px2, py2, pz2;
    {
        unsigned ux = __float_as_uint(px), uy = __float_as_uint(py), uz = __float_as_uint(pz);
        asm("mov.b64 %0, {%1, %1};" : "=l"(px2) : "r"(ux));
        asm("mov.b64 %0, {%1, %1};" : "=l"(py2) : "r"(uy));
        asm("mov.b64 %0, {%1, %1};" : "=l"(pz2) : "r"(uz));
    }

    // ---- nearest-neighbor: min over 512 GT candidates, 2 per iteration ----
    const ulonglong2* sp = (const ulonglong2*)sg;  // 2 ulonglong2 per pair
    float mn0 = 3.0e38f, mn1 = 3.0e38f;
#pragma unroll 8
    for (int i = 0; i < NPAIR; i++) {
        ulonglong2 a = sp[2 * i];       // a.x = {x0,x1}, a.y = {y0,y1}
        ulonglong2 c = sp[2 * i + 1];   // c.x = {z0,z1}, c.y = {w0,w1}
        unsigned long long v;
        asm("fma.rn.f32x2 %0, %1, %2, %3;" : "=l"(v) : "l"(pz2), "l"(c.x), "l"(c.y));
        asm("fma.rn.f32x2 %0, %1, %2, %3;" : "=l"(v) : "l"(py2), "l"(a.y), "l"(v));
        asm("fma.rn.f32x2 %0, %1, %2, %3;" : "=l"(v) : "l"(px2), "l"(a.x), "l"(v));
        float v0 = __uint_as_float((unsigned)v);
        float v1 = __uint_as_float((unsigned)(v >> 32));
        mn0 = fminf(mn0, v0);
        mn1 = fminf(mn1, v1);
    }
    float dmin = sqrtf(fmaxf(pn + fminf(mn0, mn1), 0.0f));

    // ---- block reduction: sum of dmin over 512 model points ----
    red[tid] = dmin;
    __syncthreads();
#pragma unroll
    for (int s = NP / 2; s >= 32; s >>= 1) {   // fold down to 32 inclusive
        if (tid < s) red[tid] += red[tid + s];
        __syncthreads();
    }
    if (tid < 32) {
        float v = red[tid];
#pragma unroll
        for (int o = 16; o > 0; o >>= 1)
            v += __shfl_down_sync(0xFFFFFFFFu, v, o);
        if (tid == 0) {
            float add = v * (1.0f / NP);
            float sc  = pred_s[b * HW + pix];
            g_part[blk] = (add * sc - SCORING_WEIGHT * logf(sc)) * (1.0f / NBLK);
            __threadfence();
            unsigned old = atomicAdd(&g_count, 1u);
            s_last = (old == NBLK - 1);
        }
    }
    __syncthreads();

    // ---- last block finishes: reduce 408 partials + inf/nan guard ----
    if (s_last && tid < 32) {
        float v = 0.0f;
        for (int i = tid; i < NBLK; i += 32) v += __ldcg(&g_part[i]);
#pragma unroll
        for (int o = 16; o > 0; o >>= 1)
            v += __shfl_down_sync(0xFFFFFFFFu, v, o);
        if (tid == 0) {
            if (isinf(v) || isnan(v)) v = 0.0f;
            out[0] = v;
            g_count = 0;   // reset for next launch / graph replay
        }
    }
}

// ---------------------------------------------------------------------------
// Inputs (metadata order): pred_r, pred_t, pred_s, mask, gt_r, gt_t,
//                          model_xyz, cls_ids
// ---------------------------------------------------------------------------
extern "C" void kernel_launch(void* const* d_in, const int* in_sizes, int n_in,
                              void* d_out, int out_size)
{
    const float* pred_r = (const float*)d_in[0];
    const float* pred_t = (const float*)d_in[1];
    const float* pred_s = (const float*)d_in[2];
    // d_in[3] = mask (unused)
    const float* gt_r   = (const float*)d_in[4];
    const float* gt_t   = (const float*)d_in[5];
    const float* model  = (const float*)d_in[6];
    // d_in[7] = cls_ids (unused)

    fused_kernel<<<NBLK, NP>>>(pred_r, pred_t, pred_s, gt_r, gt_t, model,
                               (float*)d_out);
}

// round 4
// speedup vs baseline: 1.4398x; 1.4398x over previous
#include <cuda_runtime.h>
#include <math.h>

#define BS   8
#define HW   1024
#define STEP 20
#define NS   51            // hw // STEP
#define NP   512           // model points
#define NPAIR (NP / 2)     // 256 packed GT pairs
#define NBLK (BS * NS)     // 408 hypotheses
#define NT   128           // threads per block
#define Q    4             // model points (queries) per thread
#define SCORING_WEIGHT 0.01f

// Scratch (no allocations allowed)
__device__ float    g_part[NBLK];
__device__ unsigned g_count = 0;   // last-block-done counter; self-resetting

// ---------------------------------------------------------------------------
// One block per (batch, sample) hypothesis. 128 threads, 4 model points each.
// GT cloud packed in shared as pairs [x0,x1, y0,y1, z0,z1, w0,w1] with
// (x,y,z) = -2*g, w = |g|^2. Inner iteration (2 candidates, 4 queries):
//   2x LDS.128 (warp-broadcast) + 12x fma.rn.f32x2 + 8x FMNMX.
// Last finishing block reduces the 408 partials (threadfence + counter).
// ---------------------------------------------------------------------------
__global__ __launch_bounds__(NT) void fused_kernel(
    const float* __restrict__ pred_r,
    const float* __restrict__ pred_t,
    const float* __restrict__ pred_s,
    const float* __restrict__ gt_r,
    const float* __restrict__ gt_t,
    const float* __restrict__ model,
    float* __restrict__ out)
{
    __shared__ float sg[NP * 4];     // 8 KB: 256 pairs x 32 bytes
    __shared__ float red[NT];
    __shared__ bool  s_last;

    int blk = blockIdx.x;
    int b   = blk / NS;
    int pix = (blk % NS) * STEP;
    int tid = threadIdx.x;

    const float* m = model + b * 3 * NP;

    // ---- load this thread's Q model points ----
    float mx[Q], my[Q], mz[Q];
#pragma unroll
    for (int k = 0; k < Q; k++) {
        int p = tid + k * NT;
        mx[k] = m[p];
        my[k] = m[NP + p];
        mz[k] = m[2 * NP + p];
    }

    // ---- GT points for this thread's Q indices -> packed shared ----
    {
        const float* R = gt_r + b * 9;
        const float* T = gt_t + b * 3;
        float R0 = R[0], R1 = R[1], R2 = R[2];
        float R3 = R[3], R4 = R[4], R5 = R[5];
        float R6 = R[6], R7 = R[7], R8 = R[8];
        float T0 = T[0], T1 = T[1], T2 = T[2];
#pragma unroll
        for (int k = 0; k < Q; k++) {
            int p = tid + k * NT;
            float gx = fmaf(R0, mx[k], fmaf(R1, my[k], fmaf(R2, mz[k], T0)));
            float gy = fmaf(R3, mx[k], fmaf(R4, my[k], fmaf(R5, mz[k], T1)));
            float gz = fmaf(R6, mx[k], fmaf(R7, my[k], fmaf(R8, mz[k], T2)));
            float gn = fmaf(gx, gx, fmaf(gy, gy, gz * gz));
            float* dst = sg + 8 * (p >> 1) + (p & 1);
            dst[0] = -2.0f * gx;
            dst[2] = -2.0f * gy;
            dst[4] = -2.0f * gz;
            dst[6] = gn;
        }
    }

    // ---- pose from predictions (tiny, redundant per thread) ----
    const float* pr = pred_r + b * 4 * HW + pix;
    float q0 = pr[0], q1 = pr[HW], q2 = pr[2 * HW], q3 = pr[3 * HW];
    float inv = rsqrtf(q0 * q0 + q1 * q1 + q2 * q2 + q3 * q3);
    q0 *= inv; q1 *= inv; q2 *= inv; q3 *= inv;

    float R00 = 1.0f - 2.0f * (q2 * q2 + q3 * q3);
    float R01 = 2.0f * (q1 * q2 - q0 * q3);
    float R02 = 2.0f * (q0 * q2 + q1 * q3);
    float R10 = 2.0f * (q1 * q2 + q3 * q0);
    float R11 = 1.0f - 2.0f * (q1 * q1 + q3 * q3);
    float R12 = 2.0f * (q2 * q3 - q0 * q1);
    float R20 = 2.0f * (q1 * q3 - q0 * q2);
    float R21 = 2.0f * (q0 * q1 + q2 * q3);
    float R22 = 1.0f - 2.0f * (q1 * q1 + q2 * q2);

    const float* pt = pred_t + b * 3 * HW + pix;
    float tx = pt[0], ty = pt[HW], tz = pt[2 * HW];

    // ---- transform this thread's Q queries, pack into f32x2 broadcasts ----
    unsigned long long px2[Q], py2[Q], pz2[Q];
    float pn[Q];
#pragma unroll
    for (int k = 0; k < Q; k++) {
        float px = fmaf(R00, mx[k], fmaf(R01, my[k], fmaf(R02, mz[k], tx)));
        float py = fmaf(R10, mx[k], fmaf(R11, my[k], fmaf(R12, mz[k], ty)));
        float pz = fmaf(R20, mx[k], fmaf(R21, my[k], fmaf(R22, mz[k], tz)));
        pn[k] = fmaf(px, px, fmaf(py, py, pz * pz));
        unsigned ux = __float_as_uint(px), uy = __float_as_uint(py), uz = __float_as_uint(pz);
        asm("mov.b64 %0, {%1, %1};" : "=l"(px2[k]) : "r"(ux));
        asm("mov.b64 %0, {%1, %1};" : "=l"(py2[k]) : "r"(uy));
        asm("mov.b64 %0, {%1, %1};" : "=l"(pz2[k]) : "r"(uz));
    }

    __syncthreads();

    // ---- nearest-neighbor: min over 512 candidates for Q queries at once ----
    const ulonglong2* sp = (const ulonglong2*)sg;
    float mn0[Q], mn1[Q];
#pragma unroll
    for (int k = 0; k < Q; k++) { mn0[k] = 3.0e38f; mn1[k] = 3.0e38f; }

#pragma unroll 4
    for (int i = 0; i < NPAIR; i++) {
        ulonglong2 a = sp[2 * i];       // a.x = {x0,x1}, a.y = {y0,y1}
        ulonglong2 c = sp[2 * i + 1];   // c.x = {z0,z1}, c.y = {w0,w1}
#pragma unroll
        for (int k = 0; k < Q; k++) {
            unsigned long long v;
            asm("fma.rn.f32x2 %0, %1, %2, %3;" : "=l"(v) : "l"(pz2[k]), "l"(c.x), "l"(c.y));
            asm("fma.rn.f32x2 %0, %1, %2, %3;" : "=l"(v) : "l"(py2[k]), "l"(a.y), "l"(v));
            asm("fma.rn.f32x2 %0, %1, %2, %3;" : "=l"(v) : "l"(px2[k]), "l"(a.x), "l"(v));
            float v0 = __uint_as_float((unsigned)v);
            float v1 = __uint_as_float((unsigned)(v >> 32));
            mn0[k] = fminf(mn0[k], v0);
            mn1[k] = fminf(mn1[k], v1);
        }
    }

    float acc = 0.0f;
#pragma unroll
    for (int k = 0; k < Q; k++)
        acc += sqrtf(fmaxf(pn[k] + fminf(mn0[k], mn1[k]), 0.0f));

    // ---- block reduction: sum over the 128 threads (512 model points) ----
    red[tid] = acc;
    __syncthreads();
#pragma unroll
    for (int s = NT / 2; s >= 32; s >>= 1) {   // fold down to 32 inclusive
        if (tid < s) red[tid] += red[tid + s];
        __syncthreads();
    }
    if (tid < 32) {
        float v = red[tid];
#pragma unroll
        for (int o = 16; o > 0; o >>= 1)
            v += __shfl_down_sync(0xFFFFFFFFu, v, o);
        if (tid == 0) {
            float add = v * (1.0f / NP);
            float sc  = pred_s[b * HW + pix];
            g_part[blk] = (add * sc - SCORING_WEIGHT * logf(sc)) * (1.0f / NBLK);
            __threadfence();
            unsigned old = atomicAdd(&g_count, 1u);
            s_last = (old == NBLK - 1);
        }
    }
    __syncthreads();

    // ---- last block: reduce 408 partials + inf/nan guard ----
    if (s_last && tid < 32) {
        float v = 0.0f;
        for (int i = tid; i < NBLK; i += 32) v += __ldcg(&g_part[i]);
#pragma unroll
        for (int o = 16; o > 0; o >>= 1)
            v += __shfl_down_sync(0xFFFFFFFFu, v, o);
        if (tid == 0) {
            if (isinf(v) || isnan(v)) v = 0.0f;
            out[0] = v;
            g_count = 0;   // reset for next launch / graph replay
        }
    }
}

// ---------------------------------------------------------------------------
// Inputs (metadata order): pred_r, pred_t, pred_s, mask, gt_r, gt_t,
//                          model_xyz, cls_ids
// ---------------------------------------------------------------------------
extern "C" void kernel_launch(void* const* d_in, const int* in_sizes, int n_in,
                              void* d_out, int out_size)
{
    const float* pred_r = (const float*)d_in[0];
    const float* pred_t = (const float*)d_in[1];
    const float* pred_s = (const float*)d_in[2];
    // d_in[3] = mask (unused)
    const float* gt_r   = (const float*)d_in[4];
    const float* gt_t   = (const float*)d_in[5];
    const float* model  = (const float*)d_in[6];
    // d_in[7] = cls_ids (unused)

    fused_kernel<<<NBLK, NT>>>(pred_r, pred_t, pred_s, gt_r, gt_t, model,
                               (float*)d_out);
}

// round 5
// speedup vs baseline: 1.4568x; 1.0118x over previous
#include <cuda_runtime.h>
#include <math.h>

#define BS   8
#define HW   1024
#define STEP 20
#define NS   51            // hw // STEP
#define NP   512           // model points
#define NPAIR (NP / 2)     // 256 packed GT pairs
#define NBLK (BS * NS)     // 408 hypotheses
#define NT   256           // threads per block (2 candidate groups x 128)
#define NG   128           // threads per candidate group
#define Q    4             // model points (queries) per thread
#define SCORING_WEIGHT 0.01f

// Scratch (no allocations allowed)
__device__ float    g_part[NBLK];
__device__ unsigned g_count = 0;   // last-block-done counter; self-resetting

// ---------------------------------------------------------------------------
// One block per (batch, sample) hypothesis. 256 threads in 2 candidate-groups:
// group g = tid/128 scans GT pairs [g*128, g*128+128); every thread owns the
// same Q=4 query points (index gtid + k*128). GT cloud packed in shared as
// pairs [x0,x1, y0,y1, z0,z1, w0,w1] with (x,y,z) = -2*g, w = |g|^2.
// Inner iteration: 2x LDS.128 (broadcast) + 12x fma.rn.f32x2 + 8x FMNMX for
// 2 candidates x 4 queries. Group mins combined via shared scratch; last
// finishing block reduces the 408 partials.
// ---------------------------------------------------------------------------
__global__ __launch_bounds__(NT) void fused_kernel(
    const float* __restrict__ pred_r,
    const float* __restrict__ pred_t,
    const float* __restrict__ pred_s,
    const float* __restrict__ gt_r,
    const float* __restrict__ gt_t,
    const float* __restrict__ model,
    float* __restrict__ out)
{
    __shared__ float sg[NP * 4];     // 8 KB: 256 pairs x 32 B; reused as scratch
    __shared__ float red[NG];
    __shared__ bool  s_last;

    int blk  = blockIdx.x;
    int b    = blk / NS;
    int pix  = (blk % NS) * STEP;
    int tid  = threadIdx.x;
    int g    = tid >> 7;      // candidate group 0/1
    int gtid = tid & (NG - 1);

    const float* m = model + b * 3 * NP;

    // ---- GT points: each thread builds 2 of the 512 packed entries ----
    {
        const float* R = gt_r + b * 9;
        const float* T = gt_t + b * 3;
        float R0 = R[0], R1 = R[1], R2 = R[2];
        float R3 = R[3], R4 = R[4], R5 = R[5];
        float R6 = R[6], R7 = R[7], R8 = R[8];
        float T0 = T[0], T1 = T[1], T2 = T[2];
#pragma unroll
        for (int k = 0; k < 2; k++) {
            int p = tid + k * NT;
            float vx = m[p], vy = m[NP + p], vz = m[2 * NP + p];
            float gx = fmaf(R0, vx, fmaf(R1, vy, fmaf(R2, vz, T0)));
            float gy = fmaf(R3, vx, fmaf(R4, vy, fmaf(R5, vz, T1)));
            float gz = fmaf(R6, vx, fmaf(R7, vy, fmaf(R8, vz, T2)));
            float gn = fmaf(gx, gx, fmaf(gy, gy, gz * gz));
            float* dst = sg + 8 * (p >> 1) + (p & 1);
            dst[0] = -2.0f * gx;
            dst[2] = -2.0f * gy;
            dst[4] = -2.0f * gz;
            dst[6] = gn;
        }
    }

    // ---- pose from predictions (tiny, redundant per thread) ----
    const float* pr = pred_r + b * 4 * HW + pix;
    float q0 = pr[0], q1 = pr[HW], q2 = pr[2 * HW], q3 = pr[3 * HW];
    float inv = rsqrtf(q0 * q0 + q1 * q1 + q2 * q2 + q3 * q3);
    q0 *= inv; q1 *= inv; q2 *= inv; q3 *= inv;

    float R00 = 1.0f - 2.0f * (q2 * q2 + q3 * q3);
    float R01 = 2.0f * (q1 * q2 - q0 * q3);
    float R02 = 2.0f * (q0 * q2 + q1 * q3);
    float R10 = 2.0f * (q1 * q2 + q3 * q0);
    float R11 = 1.0f - 2.0f * (q1 * q1 + q3 * q3);
    float R12 = 2.0f * (q2 * q3 - q0 * q1);
    float R20 = 2.0f * (q1 * q3 - q0 * q2);
    float R21 = 2.0f * (q0 * q1 + q2 * q3);
    float R22 = 1.0f - 2.0f * (q1 * q1 + q2 * q2);

    const float* pt = pred_t + b * 3 * HW + pix;
    float tx = pt[0], ty = pt[HW], tz = pt[2 * HW];

    // ---- transform this thread's Q query points, pack f32x2 broadcasts ----
    unsigned long long px2[Q], py2[Q], pz2[Q];
    float pn[Q];
#pragma unroll
    for (int k = 0; k < Q; k++) {
        int p = gtid + k * NG;
        float vx = m[p], vy = m[NP + p], vz = m[2 * NP + p];
        float px = fmaf(R00, vx, fmaf(R01, vy, fmaf(R02, vz, tx)));
        float py = fmaf(R10, vx, fmaf(R11, vy, fmaf(R12, vz, ty)));
        float pz = fmaf(R20, vx, fmaf(R21, vy, fmaf(R22, vz, tz)));
        pn[k] = fmaf(px, px, fmaf(py, py, pz * pz));
        unsigned ux = __float_as_uint(px), uy = __float_as_uint(py), uz = __float_as_uint(pz);
        asm("mov.b64 %0, {%1, %1};" : "=l"(px2[k]) : "r"(ux));
        asm("mov.b64 %0, {%1, %1};" : "=l"(py2[k]) : "r"(uy));
        asm("mov.b64 %0, {%1, %1};" : "=l"(pz2[k]) : "r"(uz));
    }

    __syncthreads();

    // ---- nearest-neighbor over this group's 128 candidate pairs ----
    const ulonglong2* sp = (const ulonglong2*)sg + g * (NPAIR / 2) * 2;
    float mn0[Q], mn1[Q];
#pragma unroll
    for (int k = 0; k < Q; k++) { mn0[k] = 3.0e38f; mn1[k] = 3.0e38f; }

#pragma unroll 4
    for (int i = 0; i < NPAIR / 2; i++) {
        ulonglong2 a = sp[2 * i];       // a.x = {x0,x1}, a.y = {y0,y1}
        ulonglong2 c = sp[2 * i + 1];   // c.x = {z0,z1}, c.y = {w0,w1}
#pragma unroll
        for (int k = 0; k < Q; k++) {
            unsigned long long v;
            asm("fma.rn.f32x2 %0, %1, %2, %3;" : "=l"(v) : "l"(pz2[k]), "l"(c.x), "l"(c.y));
            asm("fma.rn.f32x2 %0, %1, %2, %3;" : "=l"(v) : "l"(py2[k]), "l"(a.y), "l"(v));
            asm("fma.rn.f32x2 %0, %1, %2, %3;" : "=l"(v) : "l"(px2[k]), "l"(a.x), "l"(v));
            float v0 = __uint_as_float((unsigned)v);
            float v1 = __uint_as_float((unsigned)(v >> 32));
            mn0[k] = fminf(mn0[k], v0);
            mn1[k] = fminf(mn1[k], v1);
        }
    }

    float mnc[Q];
#pragma unroll
    for (int k = 0; k < Q; k++) mnc[k] = fminf(mn0[k], mn1[k]);

    // ---- combine the two candidate-groups' mins (reuse sg as scratch) ----
    __syncthreads();                    // everyone done reading sg
    if (g == 1) {
#pragma unroll
        for (int k = 0; k < Q; k++) sg[gtid + k * NG] = mnc[k];
    }
    __syncthreads();

    float acc = 0.0f;
    if (g == 0) {
#pragma unroll
        for (int k = 0; k < Q; k++) {
            float m2 = fminf(mnc[k], sg[gtid + k * NG]);
            acc += sqrtf(fmaxf(pn[k] + m2, 0.0f));
        }
        red[gtid] = acc;
    }
    __syncthreads();

    // ---- reduce 128 partial sums (group 0's values) ----
    if (tid < 64) red[tid] += red[tid + 64];
    __syncthreads();
    if (tid < 32) {
        float v = red[tid] + red[tid + 32];
#pragma unroll
        for (int o = 16; o > 0; o >>= 1)
            v += __shfl_down_sync(0xFFFFFFFFu, v, o);
        if (tid == 0) {
            float add = v * (1.0f / NP);
            float sc  = pred_s[b * HW + pix];
            g_part[blk] = (add * sc - SCORING_WEIGHT * logf(sc)) * (1.0f / NBLK);
            __threadfence();
            unsigned old = atomicAdd(&g_count, 1u);
            s_last = (old == NBLK - 1);
        }
    }
    __syncthreads();

    // ---- last block: reduce 408 partials + inf/nan guard ----
    if (s_last && tid < 32) {
        float v = 0.0f;
        for (int i = tid; i < NBLK; i += 32) v += __ldcg(&g_part[i]);
#pragma unroll
        for (int o = 16; o > 0; o >>= 1)
            v += __shfl_down_sync(0xFFFFFFFFu, v, o);
        if (tid == 0) {
            if (isinf(v) || isnan(v)) v = 0.0f;
            out[0] = v;
            g_count = 0;   // reset for next launch / graph replay
        }
    }
}

// ---------------------------------------------------------------------------
// Inputs (metadata order): pred_r, pred_t, pred_s, mask, gt_r, gt_t,
//                          model_xyz, cls_ids
// ---------------------------------------------------------------------------
extern "C" void kernel_launch(void* const* d_in, const int* in_sizes, int n_in,
                              void* d_out, int out_size)
{
    const float* pred_r = (const float*)d_in[0];
    const float* pred_t = (const float*)d_in[1];
    const float* pred_s = (const float*)d_in[2];
    // d_in[3] = mask (unused)
    const float* gt_r   = (const float*)d_in[4];
    const float* gt_t   = (const float*)d_in[5];
    const float* model  = (const float*)d_in[6];
    // d_in[7] = cls_ids (unused)

    fused_kernel<<<NBLK, NT>>>(pred_r, pred_t, pred_s, gt_r, gt_t, model,
                               (float*)d_out);
}